// round 3
// baseline (speedup 1.0000x reference)
#include <cuda_runtime.h>
#include <math.h>

// Problem constants (hardcoded in reference)
#define B 32
#define D 128
#define K 512
#define C 10
#define NT 512          // threads per CTA
#define DCHUNK 32       // D / 4 d-groups

// fac2 = mu @ V  [10, 512] — the only cross-CTA intermediate
__device__ float g_fac2[C * K];
__device__ int g_ready = 0;   // producers done (target C)
__device__ int g_done  = 0;   // consumers done (target B)

__device__ __forceinline__ int ld_acquire_gpu(const int* p) {
    int v;
    asm volatile("ld.acquire.gpu.s32 %0, [%1];" : "=r"(v) : "l"(p) : "memory");
    return v;
}

// 42 CTAs x 512 threads:
//   CTA 0..31  : consumer b — fac1 row b (d split over 4 warp-groups), wait
//                for fac2, dot + log_softmax, write out[b].
//   CTA 32..41 : producer c — fac2 row c (d split over 4 warp-groups), publish.
__global__ __launch_bounds__(NT, 1) void fused_kernel(
    const float* __restrict__ x,
    const float* __restrict__ mu,
    const float* __restrict__ U,
    const float* __restrict__ V,
    float* __restrict__ out) {
    __shared__ float sx[D];
    __shared__ float part[4][K];     // per-d-group partial row (4 x 2KB)
    __shared__ float hs[16][C];      // per-warp dot partials
    __shared__ float hrow[C];

    const int t  = threadIdx.x;
    const int g  = t >> 7;           // d-group 0..3
    const int tt = t & 127;          // float4 k-slice within group

    const bool producer = (blockIdx.x >= B);
    const int row = producer ? (blockIdx.x - B) : blockIdx.x;
    const float* src = producer ? (mu + row * D) : (x + row * D);
    const float* W   = producer ? V : U;

    if (t < D) sx[t] = src[t];
    __syncthreads();

    // ---- phase 1: this CTA's factor row, d-chunk per warp-group ----
    float4 acc = make_float4(0.f, 0.f, 0.f, 0.f);
    const float* Wg = W + g * DCHUNK * K;
    const float* sg = sx + g * DCHUNK;
#pragma unroll 16
    for (int d = 0; d < DCHUNK; d++) {
        float4 w = reinterpret_cast<const float4*>(Wg + d * K)[tt];
        float sv = sg[d];
        acc.x = fmaf(sv, w.x, acc.x);
        acc.y = fmaf(sv, w.y, acc.y);
        acc.z = fmaf(sv, w.z, acc.z);
        acc.w = fmaf(sv, w.w, acc.w);
    }
    reinterpret_cast<float4*>(&part[g][tt * 4])[0] = acc;
    __syncthreads();

    if (producer) {
        // reduce 4 partials and publish fac2 row
        if (t < 128) {
            float4 a0 = reinterpret_cast<const float4*>(&part[0][t * 4])[0];
            float4 a1 = reinterpret_cast<const float4*>(&part[1][t * 4])[0];
            float4 a2 = reinterpret_cast<const float4*>(&part[2][t * 4])[0];
            float4 a3 = reinterpret_cast<const float4*>(&part[3][t * 4])[0];
            float4 r = make_float4(a0.x + a1.x + a2.x + a3.x,
                                   a0.y + a1.y + a2.y + a3.y,
                                   a0.z + a1.z + a2.z + a3.z,
                                   a0.w + a1.w + a2.w + a3.w);
            reinterpret_cast<float4*>(g_fac2 + row * K)[t] = r;
        }
        __syncthreads();
        __threadfence();
        if (t == 0) atomicAdd(&g_ready, 1);
        return;
    }

    // ---- consumer: wait for fac2 (read-only acquire polling) ----
    if (t == 0) {
        while (ld_acquire_gpu(&g_ready) < C) { }
    }
    __syncthreads();

    // ---- phase 2: thread t owns k = t ----
    const int k = t;
    const float f1 = part[0][k] + part[1][k] + part[2][k] + part[3][k];

    float p[C];
#pragma unroll
    for (int c = 0; c < C; c++)
        p[c] = f1 * g_fac2[c * K + k];

    // butterfly reduce within each warp (10 concurrent values -> ILP)
#pragma unroll
    for (int o = 16; o > 0; o >>= 1) {
#pragma unroll
        for (int c = 0; c < C; c++)
            p[c] += __shfl_xor_sync(0xffffffffu, p[c], o);
    }

    const int w    = t >> 5;
    const int lane = t & 31;
    if (lane == 0) {
#pragma unroll
        for (int c = 0; c < C; c++) hs[w][c] = p[c];
    }
    __syncthreads();

    if (t < C) {
        float h = 0.f;
#pragma unroll
        for (int w2 = 0; w2 < 16; w2++) h += hs[w2][t];
        hrow[t] = h;
    }
    __syncthreads();

    if (t == 0) {
        float h[C];
        float m = -INFINITY;
#pragma unroll
        for (int c = 0; c < C; c++) { h[c] = hrow[c]; m = fmaxf(m, h[c]); }
        float se = 0.f;
#pragma unroll
        for (int c = 0; c < C; c++) se += expf(h[c] - m);
        float lse = m + logf(se);
#pragma unroll
        for (int c = 0; c < C; c++) out[row * C + c] = h[c] - lse;

        // last consumer resets counters for the next graph replay
        if (atomicAdd(&g_done, 1) == B - 1) {
            atomicExch(&g_ready, 0);
            atomicExch(&g_done, 0);
        }
    }
}

extern "C" void kernel_launch(void* const* d_in, const int* in_sizes, int n_in,
                              void* d_out, int out_size) {
    const float* x  = (const float*)d_in[0];  // [32, 128]
    const float* mu = (const float*)d_in[1];  // [10, 128]
    const float* U  = (const float*)d_in[2];  // [128, 512]
    const float* V  = (const float*)d_in[3];  // [128, 512]
    float* out = (float*)d_out;               // [32, 10]

    fused_kernel<<<B + C, NT>>>(x, mu, U, V, out);
}

// round 4
// speedup vs baseline: 1.0476x; 1.0476x over previous
#include <cuda_runtime.h>
#include <math.h>

// Problem constants (hardcoded in reference)
#define B 32
#define D 128
#define K 512
#define C 10
#define NT 1024         // threads per CTA
#define NG 8            // d-groups per CTA
#define DCHUNK (D / NG) // 16 d-rows per group

// fac2 = mu @ V  [10, 512] — the only cross-CTA intermediate
__device__ float g_fac2[C * K];
__device__ int g_ready = 0;   // producers done (target C)
__device__ int g_done  = 0;   // consumers done (target B)

__device__ __forceinline__ int ld_acquire_gpu(const int* p) {
    int v;
    asm volatile("ld.acquire.gpu.s32 %0, [%1];" : "=r"(v) : "l"(p) : "memory");
    return v;
}
__device__ __forceinline__ void red_release_add(int* p, int v) {
    asm volatile("red.release.gpu.global.add.s32 [%0], %1;" :: "l"(p), "r"(v) : "memory");
}

// 42 CTAs x 1024 threads:
//   CTA 0..31  : consumer b — fac1 row b (d split over 8 groups), wait for
//                fac2, dot + log_softmax, write out[b].
//   CTA 32..41 : producer c — fac2 row c, publish with release semantics.
__global__ __launch_bounds__(NT, 1) void fused_kernel(
    const float* __restrict__ x,
    const float* __restrict__ mu,
    const float* __restrict__ U,
    const float* __restrict__ V,
    float* __restrict__ out) {
    __shared__ float sx[D];
    __shared__ float part[NG][K];    // per-d-group partial row (8 x 2KB)
    __shared__ float hs[32][5];      // per-warp dot partials (half-block x 5 c's)
    __shared__ float hrow[C];

    const int t  = threadIdx.x;
    const int g  = t >> 7;           // d-group 0..7
    const int tt = t & 127;          // float4 k-slice within group

    const bool producer = (blockIdx.x >= B);
    const int row = producer ? (blockIdx.x - B) : blockIdx.x;
    const float* src = producer ? (mu + row * D) : (x + row * D);
    const float* W   = producer ? V : U;

    if (t < D) sx[t] = src[t];
    __syncthreads();

    // ---- phase 1: this CTA's factor row, 16-d chunk per group ----
    float4 acc = make_float4(0.f, 0.f, 0.f, 0.f);
    const float* Wg = W + g * DCHUNK * K;
    const float* sg = sx + g * DCHUNK;
#pragma unroll
    for (int d = 0; d < DCHUNK; d++) {
        float4 w = reinterpret_cast<const float4*>(Wg + d * K)[tt];
        float sv = sg[d];
        acc.x = fmaf(sv, w.x, acc.x);
        acc.y = fmaf(sv, w.y, acc.y);
        acc.z = fmaf(sv, w.z, acc.z);
        acc.w = fmaf(sv, w.w, acc.w);
    }
    reinterpret_cast<float4*>(&part[g][tt * 4])[0] = acc;
    __syncthreads();

    if (producer) {
        // reduce 8 partials and publish fac2 row
        if (t < 128) {
            float4 r = make_float4(0.f, 0.f, 0.f, 0.f);
#pragma unroll
            for (int gg = 0; gg < NG; gg++) {
                float4 a = reinterpret_cast<const float4*>(&part[gg][t * 4])[0];
                r.x += a.x; r.y += a.y; r.z += a.z; r.w += a.w;
            }
            reinterpret_cast<float4*>(g_fac2 + row * K)[t] = r;
        }
        __syncthreads();
        if (t == 0) red_release_add(&g_ready, 1);   // release: orders the row stores
        return;
    }

    // ---- consumer: wait for all 10 fac2 rows (read-only acquire poll) ----
    if (t == 0) {
        while (ld_acquire_gpu(&g_ready) < C) { }
    }
    __syncthreads();

    // ---- phase 2: half-block h owns classes [5h, 5h+5), thread covers k = t&511
    const int half = t >> 9;             // 0 or 1
    const int k    = t & (K - 1);
    float f1 = 0.f;
#pragma unroll
    for (int gg = 0; gg < NG; gg++) f1 += part[gg][k];

    float p[5];
#pragma unroll
    for (int c = 0; c < 5; c++)
        p[c] = f1 * g_fac2[(half * 5 + c) * K + k];

#pragma unroll
    for (int o = 16; o > 0; o >>= 1) {
#pragma unroll
        for (int c = 0; c < 5; c++)
            p[c] += __shfl_xor_sync(0xffffffffu, p[c], o);
    }

    const int w    = t >> 5;             // warp 0..31 (warps 0-15: c 0-4, 16-31: c 5-9)
    const int lane = t & 31;
    if (lane == 0) {
#pragma unroll
        for (int c = 0; c < 5; c++) hs[w][c] = p[c];
    }
    __syncthreads();

    if (t < C) {
        const int base = (t < 5) ? 0 : 16;   // which warp half holds this class
        const int col  = (t < 5) ? t : (t - 5);
        float h = 0.f;
#pragma unroll
        for (int w2 = 0; w2 < 16; w2++) h += hs[base + w2][col];
        hrow[t] = h;
    }
    __syncthreads();

    if (t == 0) {
        float h[C];
        float m = -INFINITY;
#pragma unroll
        for (int c = 0; c < C; c++) { h[c] = hrow[c]; m = fmaxf(m, h[c]); }
        float se = 0.f;
#pragma unroll
        for (int c = 0; c < C; c++) se += expf(h[c] - m);
        float lse = m + logf(se);
#pragma unroll
        for (int c = 0; c < C; c++) out[row * C + c] = h[c] - lse;

        // last consumer resets counters for the next graph replay
        if (atomicAdd(&g_done, 1) == B - 1) {
            atomicExch(&g_ready, 0);
            atomicExch(&g_done, 0);
        }
    }
}

extern "C" void kernel_launch(void* const* d_in, const int* in_sizes, int n_in,
                              void* d_out, int out_size) {
    const float* x  = (const float*)d_in[0];  // [32, 128]
    const float* mu = (const float*)d_in[1];  // [10, 128]
    const float* U  = (const float*)d_in[2];  // [128, 512]
    const float* V  = (const float*)d_in[3];  // [128, 512]
    float* out = (float*)d_out;               // [32, 10]

    fused_kernel<<<B + C, NT>>>(x, mu, U, V, out);
}